// round 15
// baseline (speedup 1.0000x reference)
#include <cuda_runtime.h>
#include <cuda_bf16.h>
#include <math.h>
#include <stdint.h>

#define Bn 2
#define Cn 64
#define Hn 320
#define Wn 640
#define TFn 16
#define HIDDEN 48
#define GROUPS 8
#define CPG 6
#define IN_CH 188
#define XST 192
#define HW (Hn*Wn)
#define GN_N (CPG*HW)
#define BHW (Bn*HW)
#define NT5 (Bn*Hn*5)

typedef unsigned long long ull;

#define PACK2(d, lo, hi) asm("mov.b64 %0, {%1,%2};" : "=l"(d) : "f"(lo), "f"(hi))
#define UNPACK2(lo, hi, v) asm("mov.b64 {%0,%1}, %2;" : "=f"(lo), "=f"(hi) : "l"(v))
#define FMA2(acc, a, b)  asm("fma.rn.f32x2 %0, %1, %2, %0;" : "+l"(acc) : "l"(a), "l"(b))

// Ampere-era bf16 HMMA — available on baseline compute_103.
#define MMA_BF16(c, a0,a1,a2,a3, b0,b1) \
  asm volatile("mma.sync.aligned.m16n8k16.row.col.f32.bf16.bf16.f32 " \
      "{%0,%1,%2,%3}, {%4,%5,%6,%7}, {%8,%9}, {%0,%1,%2,%3};" \
      : "+f"((c)[0]),"+f"((c)[1]),"+f"((c)[2]),"+f"((c)[3]) \
      : "r"(a0),"r"(a1),"r"(a2),"r"(a3), "r"(b0),"r"(b1))

__device__ __forceinline__ uint32_t split_pack(float v) {
    __nv_bfloat16 h = __float2bfloat16(v);
    __nv_bfloat16 l = __float2bfloat16(v - __bfloat162float(h));
    return (uint32_t)__bfloat16_as_ushort(h) | ((uint32_t)__bfloat16_as_ushort(l) << 16);
}
__device__ __forceinline__ uint32_t bf16hi(float a, float b) {
    return (uint32_t)__bfloat16_as_ushort(__float2bfloat16(a)) |
           ((uint32_t)__bfloat16_as_ushort(__float2bfloat16(b)) << 16);
}

// ---------------- scratch ----------------
__device__ __align__(16) uint32_t g_xs[(size_t)Bn*HW*XST];
__device__ __align__(16) uint32_t g_hs[(size_t)Bn*HW*HIDDEN];
__device__ __align__(16) uint32_t g_ct[(size_t)Bn*HW*40];
__device__ float  g_h1[(size_t)Bn*HIDDEN*HW];
__device__ float  g_h2[(size_t)Bn*HIDDEN*HW];
__device__ double g_stats[Bn*GROUPS*2];
__device__ float  g_scale[Bn*HIDDEN];
__device__ float  g_shift[Bn*HIDDEN];
// B fragments: [tap][chunk][ks][nb][lane] -> uint4 {bhi0,bhi1,blo0,blo1}
__device__ uint4 g_Bf1[9*4*3*6*32];
__device__ uint4 g_Bf2[9*1*3*6*32];
__device__ uint4 g_Bf3[9*1*3*6*32];

// ---------------- B fragment repack ----------------
template<int IN, int NCHUNK>
__global__ void repack_frag_kernel(const float* __restrict__ w, uint4* __restrict__ dst)
{
    int idx = blockIdx.x*256 + threadIdx.x;
    if (idx >= 9*NCHUNK*3*6*32) return;
    int lane = idx & 31, t = idx >> 5;
    int nb = t % 6; t /= 6;
    int ks = t % 3; t /= 3;
    int chunk = t % NCHUNK;
    int tap = t / NCHUNK;
    int n  = nb*8 + (lane >> 2);
    int k0 = chunk*48 + ks*16 + (lane & 3)*2;
    float v[4];
#pragma unroll
    for (int j = 0; j < 4; j++) {
        int k = k0 + ((j >> 1) ? 8 : 0) + (j & 1);
        v[j] = (k < IN) ? w[((size_t)n*IN + k)*9 + tap] : 0.f;
    }
    float h0 = __bfloat162float(__float2bfloat16(v[0]));
    float h1 = __bfloat162float(__float2bfloat16(v[1]));
    float h2 = __bfloat162float(__float2bfloat16(v[2]));
    float h3 = __bfloat162float(__float2bfloat16(v[3]));
    dst[idx] = make_uint4(bf16hi(v[0], v[1]), bf16hi(v[2], v[3]),
                          bf16hi(v[0]-h0, v[1]-h1), bf16hi(v[2]-h2, v[3]-h3));
}

// ---------------- build x: double-buffered srow, 1 barrier/group ----------------
__global__ void __launch_bounds__(Wn, 2) build_x_kernel(
    const float* __restrict__ dm, const float* __restrict__ sx,
    const float* __restrict__ sy, const float* __restrict__ feat,
    const float* __restrict__ conf, const float* __restrict__ fL,
    const float* __restrict__ fR)
{
    __shared__ float srow[2][8*Wn];
    const int b = blockIdx.x / Hn, y = blockIdx.x % Hn, x = threadIdx.x;
    const int prow = b*HW + y*Wn;
    const float dval = dm[prow + x];
    int i0[5], i1[5]; float fr[5];
#pragma unroll
    for (int i = 0; i < 5; i++) {
        float xs = fminf(fmaxf((float)x - dval - (float)(i-2), 0.f), (float)(Wn-1));
        float f0 = floorf(xs);
        i0[i] = (int)f0; fr[i] = xs - f0; i1[i] = min(i0[i]+1, Wn-1);
    }
    uint32_t* xb = g_xs + ((size_t)(b*Hn + y)*Wn + x)*XST;
    uint32_t* ct = g_ct + (size_t)(b*Hn + y)*Wn*40 + x;
    const float* fLp = fL + (size_t)b*Cn*HW + (size_t)y*Wn + x;
    const float* fRp = fR + (size_t)b*Cn*HW + (size_t)y*Wn;

    // prologue: group 0 -> buffer 0
#pragma unroll
    for (int j = 0; j < 8; j++) srow[0][j*Wn + x] = fRp[(size_t)j*HW + x];
    __syncthreads();

    for (int g = 0; g < 8; g++) {
        const int cur = g & 1;
        float tv[8];
        if (g < 7) {
#pragma unroll
            for (int j = 0; j < 8; j++)
                tv[j] = fRp[(size_t)((g+1)*8 + j)*HW + x];
        }
        float acc[5] = {0.f,0.f,0.f,0.f,0.f};
        uint32_t flw[8], wpw[8];
#pragma unroll
        for (int j = 0; j < 8; j++) {
            const float fl = fLp[(size_t)(g*8+j)*HW];
            flw[j] = split_pack(fl);
#pragma unroll
            for (int i = 0; i < 5; i++) {
                float v = srow[cur][j*Wn+i0[i]]*(1.f-fr[i]) + srow[cur][j*Wn+i1[i]]*fr[i];
                acc[i] += fl*v;
                if (i == 2) wpw[j] = split_pack(v);
            }
        }
        *(uint4*)(xb + g*8)     = make_uint4(flw[0], flw[1], flw[2], flw[3]);
        *(uint4*)(xb + g*8 + 4) = make_uint4(flw[4], flw[5], flw[6], flw[7]);
        *(uint4*)(xb + 64 + g*8)     = make_uint4(wpw[0], wpw[1], wpw[2], wpw[3]);
        *(uint4*)(xb + 64 + g*8 + 4) = make_uint4(wpw[4], wpw[5], wpw[6], wpw[7]);
#pragma unroll
        for (int i = 0; i < 5; i++)
            ct[(size_t)(g*5 + i)*Wn] = split_pack(acc[i]*0.125f);
        if (g < 7) {
#pragma unroll
            for (int j = 0; j < 8; j++) srow[cur ^ 1][j*Wn + x] = tv[j];
        }
        __syncthreads();
    }
#pragma unroll
    for (int j = 0; j < TFn; j += 4) {
        uint32_t f0 = split_pack(feat[((size_t)b*TFn + j  )*HW + y*Wn + x]);
        uint32_t f1 = split_pack(feat[((size_t)b*TFn + j+1)*HW + y*Wn + x]);
        uint32_t f2 = split_pack(feat[((size_t)b*TFn + j+2)*HW + y*Wn + x]);
        uint32_t f3 = split_pack(feat[((size_t)b*TFn + j+3)*HW + y*Wn + x]);
        *(uint4*)(xb + 128 + j) = make_uint4(f0, f1, f2, f3);
    }
    *(uint4*)(xb + 144) = make_uint4(split_pack(dval), split_pack(sx[prow+x]),
                                     split_pack(sy[prow+x]), split_pack(conf[prow+x]));
    *(uint4*)(xb + 188) = make_uint4(0,0,0,0);
}

// ---------------- corr transpose: g_ct (coalesced) -> packed slots 148..187 ----
__global__ void __launch_bounds__(256) corr_pack_kernel()
{
    const int idx = blockIdx.x*256 + threadIdx.x;
    const uint32_t* ct = g_ct + ((size_t)(idx / Wn))*Wn*40 + (idx % Wn);
    uint32_t w[40];
#pragma unroll
    for (int c = 0; c < 40; c++) w[c] = ct[(size_t)c*Wn];
    uint4* op = (uint4*)(g_xs + (size_t)idx*XST + 148);
#pragma unroll
    for (int i = 0; i < 10; i++)
        op[i] = make_uint4(w[4*i], w[4*i+1], w[4*i+2], w[4*i+3]);
}

// ---------------- HMMA conv: 256 thr, 2 CTAs/SM, fused GN stats ----------------
template<int NCHUNK, int CHS>
__global__ void __launch_bounds__(256, 2) conv_hmma_kernel(
    const uint32_t* __restrict__ xin, const uint4* __restrict__ Bf,
    float* __restrict__ out)
{
    __shared__ float s_gs[GROUPS], s_gq[GROUPS];
    const int lane = threadIdx.x & 31, wrp = threadIdx.x >> 5;
    const int t = blockIdx.x;
    const int b = t / (Hn*5);
    const int r = t % (Hn*5);
    const int y = r / 5;
    const int x0 = (r % 5)*128 + wrp*16;
    const int r0 = lane >> 2;
    const int cq = (lane & 3)*2;

    if (threadIdx.x < GROUPS) { s_gs[threadIdx.x] = 0.f; s_gq[threadIdx.x] = 0.f; }
    __syncthreads();

    float acc[6][4];
#pragma unroll
    for (int nb = 0; nb < 6; nb++)
#pragma unroll
        for (int j = 0; j < 4; j++) acc[nb][j] = 0.f;

    const uint4* Bp = Bf + lane;

#pragma unroll
    for (int tap = 0; tap < 9; tap++) {
        const int dy = tap/3, dx = tap%3;
        const int gy = y + dy - 1;
        if (gy < 0 || gy >= Hn) { Bp += NCHUNK*3*6*32; continue; }
        const int gx0 = x0 + r0 + dx - 1;
        const int gx1 = gx0 + 8;
        const bool v0 = (gx0 >= 0) && (gx0 < Wn);
        const bool v1 = (gx1 < Wn);
        const uint32_t* p0 = xin + ((size_t)(b*Hn + gy)*Wn + (v0 ? gx0 : 0))*CHS;
        const uint32_t* p1 = xin + ((size_t)(b*Hn + gy)*Wn + (v1 ? gx1 : 0))*CHS;
#pragma unroll
        for (int chunk = 0; chunk < NCHUNK; chunk++) {
#pragma unroll
            for (int ks = 0; ks < 3; ks++) {
                const int c = chunk*48 + ks*16 + cq;
                uint2 z = make_uint2(0u, 0u);
                uint2 w00 = v0 ? *(const uint2*)(p0 + c)     : z;
                uint2 w01 = v0 ? *(const uint2*)(p0 + c + 8) : z;
                uint2 w10 = v1 ? *(const uint2*)(p1 + c)     : z;
                uint2 w11 = v1 ? *(const uint2*)(p1 + c + 8) : z;
                uint32_t ah0 = __byte_perm(w00.x, w00.y, 0x5410);
                uint32_t al0 = __byte_perm(w00.x, w00.y, 0x7632);
                uint32_t ah1 = __byte_perm(w10.x, w10.y, 0x5410);
                uint32_t al1 = __byte_perm(w10.x, w10.y, 0x7632);
                uint32_t ah2 = __byte_perm(w01.x, w01.y, 0x5410);
                uint32_t al2 = __byte_perm(w01.x, w01.y, 0x7632);
                uint32_t ah3 = __byte_perm(w11.x, w11.y, 0x5410);
                uint32_t al3 = __byte_perm(w11.x, w11.y, 0x7632);
#pragma unroll
                for (int nb = 0; nb < 6; nb++) {
                    uint4 bb = Bp[nb*32];
                    MMA_BF16(acc[nb], ah0, ah1, ah2, ah3, bb.x, bb.y);
                    MMA_BF16(acc[nb], ah0, ah1, ah2, ah3, bb.z, bb.w);
                    MMA_BF16(acc[nb], al0, al1, al2, al3, bb.x, bb.y);
                }
                Bp += 6*32;
            }
        }
    }

    // ---- store outputs ----
    const int px0 = x0 + r0, px1 = px0 + 8;
    float* ob = out + (size_t)b*HIDDEN*HW + (size_t)y*Wn;
#pragma unroll
    for (int nb = 0; nb < 6; nb++) {
        const int n0 = nb*8 + cq;
        ob[(size_t)n0*HW + px0]     = acc[nb][0];
        ob[(size_t)(n0+1)*HW + px0] = acc[nb][1];
        ob[(size_t)n0*HW + px1]     = acc[nb][2];
        ob[(size_t)(n0+1)*HW + px1] = acc[nb][3];
    }

    // ---- fused GN partial stats ----
    float cs[12], cqv[12];
#pragma unroll
    for (int nb = 0; nb < 6; nb++) {
        cs[2*nb]   = acc[nb][0] + acc[nb][2];
        cs[2*nb+1] = acc[nb][1] + acc[nb][3];
        cqv[2*nb]   = acc[nb][0]*acc[nb][0] + acc[nb][2]*acc[nb][2];
        cqv[2*nb+1] = acc[nb][1]*acc[nb][1] + acc[nb][3]*acc[nb][3];
    }
#pragma unroll
    for (int o = 16; o >= 4; o >>= 1) {
#pragma unroll
        for (int i = 0; i < 12; i++) {
            cs[i]  += __shfl_xor_sync(0xFFFFFFFFu, cs[i],  o);
            cqv[i] += __shfl_xor_sync(0xFFFFFFFFu, cqv[i], o);
        }
    }
    if (r0 == 0) {
#pragma unroll
        for (int i = 0; i < 12; i++) {
            const int ch = (i >> 1)*8 + cq + (i & 1);
            atomicAdd(&s_gs[ch / CPG], cs[i]);
            atomicAdd(&s_gq[ch / CPG], cqv[i]);
        }
    }
    __syncthreads();
    if (threadIdx.x < GROUPS) {
        atomicAdd(&g_stats[(b*GROUPS + threadIdx.x)*2 + 0], (double)s_gs[threadIdx.x]);
        atomicAdd(&g_stats[(b*GROUPS + threadIdx.x)*2 + 1], (double)s_gq[threadIdx.x]);
    }
}

// ---------------- GN stats finalize ----------------
__global__ void zero_stats_kernel() {
    if (threadIdx.x < Bn*GROUPS*2) g_stats[threadIdx.x] = 0.0;
}
__global__ void finalize_stats_kernel(const float* __restrict__ gamma, const float* __restrict__ beta)
{
    const int i = threadIdx.x;
    if (i >= Bn*HIDDEN) return;
    const int b = i / HIDDEN, c = i % HIDDEN, g = c / CPG;
    double mean = g_stats[(b*GROUPS+g)*2+0] / (double)GN_N;
    double var  = g_stats[(b*GROUPS+g)*2+1] / (double)GN_N - mean*mean;
    float inv = (float)rsqrt(var + 1e-5);
    float sc = gamma[c]*inv;
    g_scale[i] = sc;
    g_shift[i] = beta[c] - (float)mean*sc;
}

// ---------------- GN+SiLU -> packed NHWC (stride 48) ----------------
__global__ void __launch_bounds__(256) hsplit_kernel(const float* __restrict__ h, uint32_t* __restrict__ dst)
{
    const int idx = blockIdx.x*256 + threadIdx.x;
    const int b = idx / HW, rem = idx % HW;
    const float* hp = h + (size_t)b*HIDDEN*HW + rem;
    const float* scb = g_scale + b*HIDDEN;
    const float* shb = g_shift + b*HIDDEN;
    uint32_t w[HIDDEN];
#pragma unroll
    for (int c = 0; c < HIDDEN; c++) {
        float z = hp[(size_t)c*HW]*scb[c] + shb[c];
        w[c] = split_pack(z / (1.f + expf(-z)));
    }
    uint4* op = (uint4*)(dst + (size_t)idx*HIDDEN);
#pragma unroll
    for (int i = 0; i < 12; i++) op[i] = make_uint4(w[4*i], w[4*i+1], w[4*i+2], w[4*i+3]);
}

// ---------------- heads ----------------
__global__ void __launch_bounds__(256) heads_kernel(
    const float* __restrict__ h,
    const float* __restrict__ dm, const float* __restrict__ sxp,
    const float* __restrict__ syp, const float* __restrict__ feat,
    const float* __restrict__ conf,
    const float* __restrict__ hd_w,  const float* __restrict__ hd_b,
    const float* __restrict__ hsx_w, const float* __restrict__ hsx_b,
    const float* __restrict__ hsy_w, const float* __restrict__ hsy_b,
    const float* __restrict__ hc_w,  const float* __restrict__ hc_b,
    const float* __restrict__ hf_w,  const float* __restrict__ hf_b,
    float* __restrict__ out)
{
    __shared__ __align__(16) float2 wsmT[HIDDEN*10];
    __shared__ float bia[20];
    __shared__ float sc[HIDDEN], sh[HIDDEN];
    const int tid = threadIdx.x, b = blockIdx.y;
    for (int idx = tid; idx < 10*HIDDEN; idx += 256) {
        int c = idx / 10, q = idx % 10;
        float w[2];
#pragma unroll
        for (int j = 0; j < 2; j++) {
            int o = 2*q + j;
            if (o == 0)      w[j] = hd_w[c];
            else if (o == 1) w[j] = hsx_w[c];
            else if (o == 2) w[j] = hsy_w[c];
            else if (o == 3) w[j] = hc_w[c];
            else             w[j] = hf_w[(o-4)*HIDDEN + c];
        }
        wsmT[idx] = make_float2(w[0], w[1]);
    }
    if (tid < 20)
        bia[tid] = (tid==0) ? hd_b[0] : (tid==1) ? hsx_b[0] : (tid==2) ? hsy_b[0]
                 : (tid==3) ? hc_b[0] : hf_b[tid-4];
    if (tid < HIDDEN) { sc[tid] = g_scale[b*HIDDEN + tid]; sh[tid] = g_shift[b*HIDDEN + tid]; }
    __syncthreads();

    const int rem = blockIdx.x*256 + tid;
    const float* hp = h + (size_t)b*HIDDEN*HW + rem;
    ull acc[10];
#pragma unroll
    for (int q = 0; q < 10; q++) acc[q] = 0ull;
#pragma unroll 4
    for (int c = 0; c < HIDDEN; c++) {
        float z = hp[(size_t)c*HW]*sc[c] + sh[c];
        float a = z / (1.f + expf(-z));
        ull da; PACK2(da, a, a);
        const ull* wrow = (const ull*)&wsmT[c*10];
        ulonglong2 w01 = *(const ulonglong2*)(wrow + 0);
        ulonglong2 w23 = *(const ulonglong2*)(wrow + 2);
        ulonglong2 w45 = *(const ulonglong2*)(wrow + 4);
        ulonglong2 w67 = *(const ulonglong2*)(wrow + 6);
        ulonglong2 w89 = *(const ulonglong2*)(wrow + 8);
        FMA2(acc[0], w01.x, da); FMA2(acc[1], w01.y, da);
        FMA2(acc[2], w23.x, da); FMA2(acc[3], w23.y, da);
        FMA2(acc[4], w45.x, da); FMA2(acc[5], w45.y, da);
        FMA2(acc[6], w67.x, da); FMA2(acc[7], w67.y, da);
        FMA2(acc[8], w89.x, da); FMA2(acc[9], w89.y, da);
    }
    float ao[20];
#pragma unroll
    for (int q = 0; q < 10; q++) UNPACK2(ao[2*q], ao[2*q+1], acc[q]);
    const int p = b*HW + rem;
    float t = ao[0] + bia[0] + dm[p];
    out[p] = fmaxf(t, 0.f) + log1pf(expf(-fabsf(t)));
    out[BHW   + p] = sxp[p] + (ao[1] + bia[1])*0.1f;
    out[2*BHW + p] = syp[p] + (ao[2] + bia[2])*0.1f;
#pragma unroll
    for (int j = 0; j < TFn; j++) {
        size_t fi = ((size_t)b*TFn + j)*HW + rem;
        out[3*(size_t)BHW + fi] = feat[fi] + ao[4+j] + bia[4+j];
    }
    float cz = ao[3] + bia[3] + 2.f*conf[p] - 1.f;
    out[19*(size_t)BHW + p] = 1.f / (1.f + expf(-cz));
}

// ---------------- launcher ----------------
extern "C" void kernel_launch(void* const* d_in, const int* in_sizes, int n_in,
                              void* d_out, int out_size)
{
    const float* dm   = (const float*)d_in[0];
    const float* sx   = (const float*)d_in[1];
    const float* sy   = (const float*)d_in[2];
    const float* feat = (const float*)d_in[3];
    const float* conf = (const float*)d_in[4];
    const float* fL   = (const float*)d_in[5];
    const float* fR   = (const float*)d_in[6];
    const float* w1   = (const float*)d_in[7];
    const float* w2   = (const float*)d_in[8];
    const float* w3   = (const float*)d_in[9];
    float* out = (float*)d_out;

    uint32_t *pxs, *phs; float *ph1, *ph2; uint4 *pB1, *pB2, *pB3;
    cudaGetSymbolAddress((void**)&pxs, g_xs);
    cudaGetSymbolAddress((void**)&phs, g_hs);
    cudaGetSymbolAddress((void**)&ph1, g_h1);
    cudaGetSymbolAddress((void**)&ph2, g_h2);
    cudaGetSymbolAddress((void**)&pB1, g_Bf1);
    cudaGetSymbolAddress((void**)&pB2, g_Bf2);
    cudaGetSymbolAddress((void**)&pB3, g_Bf3);

    const dim3 hgrid(HW/256, Bn);

    repack_frag_kernel<IN_CH, 4><<<(9*4*3*6*32 + 255)/256, 256>>>(w1, pB1);
    repack_frag_kernel<HIDDEN, 1><<<(9*1*3*6*32 + 255)/256, 256>>>(w2, pB2);
    repack_frag_kernel<HIDDEN, 1><<<(9*1*3*6*32 + 255)/256, 256>>>(w3, pB3);

    build_x_kernel<<<Bn*Hn, Wn>>>(dm, sx, sy, feat, conf, fL, fR);
    corr_pack_kernel<<<BHW/256, 256>>>();

    zero_stats_kernel<<<1, 64>>>();
    conv_hmma_kernel<4, XST><<<NT5, 256>>>(pxs, pB1, ph1);
    finalize_stats_kernel<<<1, 96>>>((const float*)d_in[10], (const float*)d_in[11]);
    hsplit_kernel<<<BHW/256, 256>>>(ph1, phs);

    zero_stats_kernel<<<1, 64>>>();
    conv_hmma_kernel<1, HIDDEN><<<NT5, 256>>>(phs, pB2, ph2);
    finalize_stats_kernel<<<1, 96>>>((const float*)d_in[12], (const float*)d_in[13]);
    hsplit_kernel<<<BHW/256, 256>>>(ph2, phs);

    zero_stats_kernel<<<1, 64>>>();
    conv_hmma_kernel<1, HIDDEN><<<NT5, 256>>>(phs, pB3, ph1);
    finalize_stats_kernel<<<1, 96>>>((const float*)d_in[14], (const float*)d_in[15]);

    heads_kernel<<<hgrid, 256>>>(ph1, dm, sx, sy, feat, conf,
                                 (const float*)d_in[16], (const float*)d_in[17],
                                 (const float*)d_in[18], (const float*)d_in[19],
                                 (const float*)d_in[20], (const float*)d_in[21],
                                 (const float*)d_in[22], (const float*)d_in[23],
                                 (const float*)d_in[24], (const float*)d_in[25], out);
}

// round 16
// speedup vs baseline: 1.1819x; 1.1819x over previous
#include <cuda_runtime.h>
#include <cuda_bf16.h>
#include <math.h>
#include <stdint.h>

#define Bn 2
#define Cn 64
#define Hn 320
#define Wn 640
#define TFn 16
#define HIDDEN 48
#define GROUPS 8
#define CPG 6
#define IN_CH 188
#define XST 192
#define HW (Hn*Wn)
#define GN_N (CPG*HW)
#define BHW (Bn*HW)
#define NT5 (Bn*Hn*5)

typedef unsigned long long ull;

#define PACK2(d, lo, hi) asm("mov.b64 %0, {%1,%2};" : "=l"(d) : "f"(lo), "f"(hi))
#define UNPACK2(lo, hi, v) asm("mov.b64 {%0,%1}, %2;" : "=f"(lo), "=f"(hi) : "l"(v))
#define FMA2(acc, a, b)  asm("fma.rn.f32x2 %0, %1, %2, %0;" : "+l"(acc) : "l"(a), "l"(b))

// Ampere-era bf16 HMMA — available on baseline compute_103.
#define MMA_BF16(c, a0,a1,a2,a3, b0,b1) \
  asm volatile("mma.sync.aligned.m16n8k16.row.col.f32.bf16.bf16.f32 " \
      "{%0,%1,%2,%3}, {%4,%5,%6,%7}, {%8,%9}, {%0,%1,%2,%3};" \
      : "+f"((c)[0]),"+f"((c)[1]),"+f"((c)[2]),"+f"((c)[3]) \
      : "r"(a0),"r"(a1),"r"(a2),"r"(a3), "r"(b0),"r"(b1))

__device__ __forceinline__ uint32_t split_pack(float v) {
    __nv_bfloat16 h = __float2bfloat16(v);
    __nv_bfloat16 l = __float2bfloat16(v - __bfloat162float(h));
    return (uint32_t)__bfloat16_as_ushort(h) | ((uint32_t)__bfloat16_as_ushort(l) << 16);
}
__device__ __forceinline__ uint32_t bf16hi(float a, float b) {
    return (uint32_t)__bfloat16_as_ushort(__float2bfloat16(a)) |
           ((uint32_t)__bfloat16_as_ushort(__float2bfloat16(b)) << 16);
}

// ---------------- scratch ----------------
__device__ __align__(16) uint32_t g_xs[(size_t)Bn*HW*XST];
__device__ __align__(16) uint32_t g_hs[(size_t)Bn*HW*HIDDEN];
__device__ __align__(16) uint32_t g_ct[(size_t)Bn*HW*40];
__device__ float  g_h1[(size_t)Bn*HIDDEN*HW];
__device__ float  g_h2[(size_t)Bn*HIDDEN*HW];
__device__ double g_stats[Bn*GROUPS*2];
__device__ float  g_scale[Bn*HIDDEN];
__device__ float  g_shift[Bn*HIDDEN];
// B fragments: [tap][chunk][ks][nb][lane] -> uint4 {bhi0,bhi1,blo0,blo1}
__device__ uint4 g_Bf1[9*4*3*6*32];
__device__ uint4 g_Bf2[9*1*3*6*32];
__device__ uint4 g_Bf3[9*1*3*6*32];

// ---------------- B fragment repack ----------------
template<int IN, int NCHUNK>
__global__ void repack_frag_kernel(const float* __restrict__ w, uint4* __restrict__ dst)
{
    int idx = blockIdx.x*256 + threadIdx.x;
    if (idx >= 9*NCHUNK*3*6*32) return;
    int lane = idx & 31, t = idx >> 5;
    int nb = t % 6; t /= 6;
    int ks = t % 3; t /= 3;
    int chunk = t % NCHUNK;
    int tap = t / NCHUNK;
    int n  = nb*8 + (lane >> 2);
    int k0 = chunk*48 + ks*16 + (lane & 3)*2;
    float v[4];
#pragma unroll
    for (int j = 0; j < 4; j++) {
        int k = k0 + ((j >> 1) ? 8 : 0) + (j & 1);
        v[j] = (k < IN) ? w[((size_t)n*IN + k)*9 + tap] : 0.f;
    }
    float h0 = __bfloat162float(__float2bfloat16(v[0]));
    float h1 = __bfloat162float(__float2bfloat16(v[1]));
    float h2 = __bfloat162float(__float2bfloat16(v[2]));
    float h3 = __bfloat162float(__float2bfloat16(v[3]));
    dst[idx] = make_uint4(bf16hi(v[0], v[1]), bf16hi(v[2], v[3]),
                          bf16hi(v[0]-h0, v[1]-h1), bf16hi(v[2]-h2, v[3]-h3));
}

// ---------------- build x: double-buffered srow, 1 barrier/group ----------------
__global__ void __launch_bounds__(Wn, 2) build_x_kernel(
    const float* __restrict__ dm, const float* __restrict__ sx,
    const float* __restrict__ sy, const float* __restrict__ feat,
    const float* __restrict__ conf, const float* __restrict__ fL,
    const float* __restrict__ fR)
{
    __shared__ float srow[2][8*Wn];
    const int b = blockIdx.x / Hn, y = blockIdx.x % Hn, x = threadIdx.x;
    const int prow = b*HW + y*Wn;
    const float dval = dm[prow + x];
    int i0[5], i1[5]; float fr[5];
#pragma unroll
    for (int i = 0; i < 5; i++) {
        float xs = fminf(fmaxf((float)x - dval - (float)(i-2), 0.f), (float)(Wn-1));
        float f0 = floorf(xs);
        i0[i] = (int)f0; fr[i] = xs - f0; i1[i] = min(i0[i]+1, Wn-1);
    }
    uint32_t* xb = g_xs + ((size_t)(b*Hn + y)*Wn + x)*XST;
    uint32_t* ct = g_ct + (size_t)(b*Hn + y)*Wn*40 + x;
    const float* fLp = fL + (size_t)b*Cn*HW + (size_t)y*Wn + x;
    const float* fRp = fR + (size_t)b*Cn*HW + (size_t)y*Wn;

#pragma unroll
    for (int j = 0; j < 8; j++) srow[0][j*Wn + x] = fRp[(size_t)j*HW + x];
    __syncthreads();

    for (int g = 0; g < 8; g++) {
        const int cur = g & 1;
        float tv[8];
        if (g < 7) {
#pragma unroll
            for (int j = 0; j < 8; j++)
                tv[j] = fRp[(size_t)((g+1)*8 + j)*HW + x];
        }
        float acc[5] = {0.f,0.f,0.f,0.f,0.f};
        uint32_t flw[8], wpw[8];
#pragma unroll
        for (int j = 0; j < 8; j++) {
            const float fl = fLp[(size_t)(g*8+j)*HW];
            flw[j] = split_pack(fl);
#pragma unroll
            for (int i = 0; i < 5; i++) {
                float v = srow[cur][j*Wn+i0[i]]*(1.f-fr[i]) + srow[cur][j*Wn+i1[i]]*fr[i];
                acc[i] += fl*v;
                if (i == 2) wpw[j] = split_pack(v);
            }
        }
        *(uint4*)(xb + g*8)     = make_uint4(flw[0], flw[1], flw[2], flw[3]);
        *(uint4*)(xb + g*8 + 4) = make_uint4(flw[4], flw[5], flw[6], flw[7]);
        *(uint4*)(xb + 64 + g*8)     = make_uint4(wpw[0], wpw[1], wpw[2], wpw[3]);
        *(uint4*)(xb + 64 + g*8 + 4) = make_uint4(wpw[4], wpw[5], wpw[6], wpw[7]);
#pragma unroll
        for (int i = 0; i < 5; i++)
            ct[(size_t)(g*5 + i)*Wn] = split_pack(acc[i]*0.125f);
        if (g < 7) {
#pragma unroll
            for (int j = 0; j < 8; j++) srow[cur ^ 1][j*Wn + x] = tv[j];
        }
        __syncthreads();
    }
#pragma unroll
    for (int j = 0; j < TFn; j += 4) {
        uint32_t f0 = split_pack(feat[((size_t)b*TFn + j  )*HW + y*Wn + x]);
        uint32_t f1 = split_pack(feat[((size_t)b*TFn + j+1)*HW + y*Wn + x]);
        uint32_t f2 = split_pack(feat[((size_t)b*TFn + j+2)*HW + y*Wn + x]);
        uint32_t f3 = split_pack(feat[((size_t)b*TFn + j+3)*HW + y*Wn + x]);
        *(uint4*)(xb + 128 + j) = make_uint4(f0, f1, f2, f3);
    }
    *(uint4*)(xb + 144) = make_uint4(split_pack(dval), split_pack(sx[prow+x]),
                                     split_pack(sy[prow+x]), split_pack(conf[prow+x]));
    *(uint4*)(xb + 188) = make_uint4(0,0,0,0);
}

// ---------------- corr transpose: g_ct (coalesced) -> packed slots 148..187 ----
__global__ void __launch_bounds__(256) corr_pack_kernel()
{
    const int idx = blockIdx.x*256 + threadIdx.x;
    const uint32_t* ct = g_ct + ((size_t)(idx / Wn))*Wn*40 + (idx % Wn);
    uint32_t w[40];
#pragma unroll
    for (int c = 0; c < 40; c++) w[c] = ct[(size_t)c*Wn];
    uint4* op = (uint4*)(g_xs + (size_t)idx*XST + 148);
#pragma unroll
    for (int i = 0; i < 10; i++)
        op[i] = make_uint4(w[4*i], w[4*i+1], w[4*i+2], w[4*i+3]);
}

// ---------------- HMMA implicit-GEMM 3x3 conv: 256 thr (8 warps), 2 CTAs/SM ----
template<int NCHUNK, int CHS>
__global__ void __launch_bounds__(256, 2) conv_hmma_kernel(
    const uint32_t* __restrict__ xin, const uint4* __restrict__ Bf,
    float* __restrict__ out)
{
    const int lane = threadIdx.x & 31, wrp = threadIdx.x >> 5;
    const int t = blockIdx.x;
    const int b = t / (Hn*5);
    const int r = t % (Hn*5);
    const int y = r / 5;
    const int x0 = (r % 5)*128 + wrp*16;
    const int r0 = lane >> 2;
    const int cq = (lane & 3)*2;

    float acc[6][4];
#pragma unroll
    for (int nb = 0; nb < 6; nb++)
#pragma unroll
        for (int j = 0; j < 4; j++) acc[nb][j] = 0.f;

    const uint4* Bp = Bf + lane;

#pragma unroll
    for (int tap = 0; tap < 9; tap++) {
        const int dy = tap/3, dx = tap%3;
        const int gy = y + dy - 1;
        if (gy < 0 || gy >= Hn) { Bp += NCHUNK*3*6*32; continue; }
        const int gx0 = x0 + r0 + dx - 1;
        const int gx1 = gx0 + 8;
        const bool v0 = (gx0 >= 0) && (gx0 < Wn);
        const bool v1 = (gx1 < Wn);
        const uint32_t* p0 = xin + ((size_t)(b*Hn + gy)*Wn + (v0 ? gx0 : 0))*CHS;
        const uint32_t* p1 = xin + ((size_t)(b*Hn + gy)*Wn + (v1 ? gx1 : 0))*CHS;
#pragma unroll
        for (int chunk = 0; chunk < NCHUNK; chunk++) {
#pragma unroll
            for (int ks = 0; ks < 3; ks++) {
                const int c = chunk*48 + ks*16 + cq;
                uint2 z = make_uint2(0u, 0u);
                uint2 w00 = v0 ? *(const uint2*)(p0 + c)     : z;
                uint2 w01 = v0 ? *(const uint2*)(p0 + c + 8) : z;
                uint2 w10 = v1 ? *(const uint2*)(p1 + c)     : z;
                uint2 w11 = v1 ? *(const uint2*)(p1 + c + 8) : z;
                uint32_t ah0 = __byte_perm(w00.x, w00.y, 0x5410);
                uint32_t al0 = __byte_perm(w00.x, w00.y, 0x7632);
                uint32_t ah1 = __byte_perm(w10.x, w10.y, 0x5410);
                uint32_t al1 = __byte_perm(w10.x, w10.y, 0x7632);
                uint32_t ah2 = __byte_perm(w01.x, w01.y, 0x5410);
                uint32_t al2 = __byte_perm(w01.x, w01.y, 0x7632);
                uint32_t ah3 = __byte_perm(w11.x, w11.y, 0x5410);
                uint32_t al3 = __byte_perm(w11.x, w11.y, 0x7632);
#pragma unroll
                for (int nb = 0; nb < 6; nb++) {
                    uint4 bb = Bp[nb*32];
                    MMA_BF16(acc[nb], ah0, ah1, ah2, ah3, bb.x, bb.y);
                    MMA_BF16(acc[nb], ah0, ah1, ah2, ah3, bb.z, bb.w);
                    MMA_BF16(acc[nb], al0, al1, al2, al3, bb.x, bb.y);
                }
                Bp += 6*32;
            }
        }
    }

    const int px0 = x0 + r0, px1 = px0 + 8;
    float* ob = out + (size_t)b*HIDDEN*HW + (size_t)y*Wn;
#pragma unroll
    for (int nb = 0; nb < 6; nb++) {
        const int n0 = nb*8 + cq;
        ob[(size_t)n0*HW + px0]     = acc[nb][0];
        ob[(size_t)(n0+1)*HW + px0] = acc[nb][1];
        ob[(size_t)n0*HW + px1]     = acc[nb][2];
        ob[(size_t)(n0+1)*HW + px1] = acc[nb][3];
    }
}

// ---------------- GN stats ----------------
__global__ void zero_stats_kernel() {
    if (threadIdx.x < Bn*GROUPS*2) g_stats[threadIdx.x] = 0.0;
}
__global__ void __launch_bounds__(256) gn_reduce_kernel(const float* __restrict__ h)
{
    const int bc = blockIdx.x, slice = blockIdx.y;
    const float4* p = (const float4*)(h + (size_t)bc*HW) + slice*6400 + threadIdx.x;
    float s0=0.f,s1=0.f,s2=0.f,s3=0.f, q0=0.f,q1=0.f,q2=0.f,q3=0.f;
#pragma unroll
    for (int k = 0; k < 25; k++) {
        float4 f = p[k*256];
        s0 += f.x; s1 += f.y; s2 += f.z; s3 += f.w;
        q0 += f.x*f.x; q1 += f.y*f.y; q2 += f.z*f.z; q3 += f.w*f.w;
    }
    double s = ((double)s0 + s1) + ((double)s2 + s3);
    double q = ((double)q0 + q1) + ((double)q2 + q3);
#pragma unroll
    for (int o = 16; o > 0; o >>= 1) {
        s += __shfl_down_sync(0xFFFFFFFFu, s, o);
        q += __shfl_down_sync(0xFFFFFFFFu, q, o);
    }
    __shared__ double ss[8], qq[8];
    if ((threadIdx.x & 31) == 0) { ss[threadIdx.x>>5] = s; qq[threadIdx.x>>5] = q; }
    __syncthreads();
    if (threadIdx.x == 0) {
        double S = 0.0, Q = 0.0;
#pragma unroll
        for (int w = 0; w < 8; w++) { S += ss[w]; Q += qq[w]; }
        const int b = bc / HIDDEN, c = bc % HIDDEN, g = c / CPG;
        atomicAdd(&g_stats[(b*GROUPS+g)*2+0], S);
        atomicAdd(&g_stats[(b*GROUPS+g)*2+1], Q);
    }
}
__global__ void finalize_stats_kernel(const float* __restrict__ gamma, const float* __restrict__ beta)
{
    const int i = threadIdx.x;
    if (i >= Bn*HIDDEN) return;
    const int b = i / HIDDEN, c = i % HIDDEN, g = c / CPG;
    double mean = g_stats[(b*GROUPS+g)*2+0] / (double)GN_N;
    double var  = g_stats[(b*GROUPS+g)*2+1] / (double)GN_N - mean*mean;
    float inv = (float)rsqrt(var + 1e-5);
    float sc = gamma[c]*inv;
    g_scale[i] = sc;
    g_shift[i] = beta[c] - (float)mean*sc;
}

// ---------------- GN+SiLU -> packed NHWC (stride 48) ----------------
__global__ void __launch_bounds__(256) hsplit_kernel(const float* __restrict__ h, uint32_t* __restrict__ dst)
{
    const int idx = blockIdx.x*256 + threadIdx.x;
    const int b = idx / HW, rem = idx % HW;
    const float* hp = h + (size_t)b*HIDDEN*HW + rem;
    const float* scb = g_scale + b*HIDDEN;
    const float* shb = g_shift + b*HIDDEN;
    uint32_t w[HIDDEN];
#pragma unroll
    for (int c = 0; c < HIDDEN; c++) {
        float z = hp[(size_t)c*HW]*scb[c] + shb[c];
        w[c] = split_pack(z / (1.f + expf(-z)));
    }
    uint4* op = (uint4*)(dst + (size_t)idx*HIDDEN);
#pragma unroll
    for (int i = 0; i < 12; i++) op[i] = make_uint4(w[4*i], w[4*i+1], w[4*i+2], w[4*i+3]);
}

// ---------------- heads ----------------
__global__ void __launch_bounds__(256) heads_kernel(
    const float* __restrict__ h,
    const float* __restrict__ dm, const float* __restrict__ sxp,
    const float* __restrict__ syp, const float* __restrict__ feat,
    const float* __restrict__ conf,
    const float* __restrict__ hd_w,  const float* __restrict__ hd_b,
    const float* __restrict__ hsx_w, const float* __restrict__ hsx_b,
    const float* __restrict__ hsy_w, const float* __restrict__ hsy_b,
    const float* __restrict__ hc_w,  const float* __restrict__ hc_b,
    const float* __restrict__ hf_w,  const float* __restrict__ hf_b,
    float* __restrict__ out)
{
    __shared__ __align__(16) float2 wsmT[HIDDEN*10];
    __shared__ float bia[20];
    __shared__ float sc[HIDDEN], sh[HIDDEN];
    const int tid = threadIdx.x, b = blockIdx.y;
    for (int idx = tid; idx < 10*HIDDEN; idx += 256) {
        int c = idx / 10, q = idx % 10;
        float w[2];
#pragma unroll
        for (int j = 0; j < 2; j++) {
            int o = 2*q + j;
            if (o == 0)      w[j] = hd_w[c];
            else if (o == 1) w[j] = hsx_w[c];
            else if (o == 2) w[j] = hsy_w[c];
            else if (o == 3) w[j] = hc_w[c];
            else             w[j] = hf_w[(o-4)*HIDDEN + c];
        }
        wsmT[idx] = make_float2(w[0], w[1]);
    }
    if (tid < 20)
        bia[tid] = (tid==0) ? hd_b[0] : (tid==1) ? hsx_b[0] : (tid==2) ? hsy_b[0]
                 : (tid==3) ? hc_b[0] : hf_b[tid-4];
    if (tid < HIDDEN) { sc[tid] = g_scale[b*HIDDEN + tid]; sh[tid] = g_shift[b*HIDDEN + tid]; }
    __syncthreads();

    const int rem = blockIdx.x*256 + tid;
    const float* hp = h + (size_t)b*HIDDEN*HW + rem;
    ull acc[10];
#pragma unroll
    for (int q = 0; q < 10; q++) acc[q] = 0ull;
#pragma unroll 4
    for (int c = 0; c < HIDDEN; c++) {
        float z = hp[(size_t)c*HW]*sc[c] + sh[c];
        float a = z / (1.f + expf(-z));
        ull da; PACK2(da, a, a);
        const ull* wrow = (const ull*)&wsmT[c*10];
        ulonglong2 w01 = *(const ulonglong2*)(wrow + 0);
        ulonglong2 w23 = *(const ulonglong2*)(wrow + 2);
        ulonglong2 w45 = *(const ulonglong2*)(wrow + 4);
        ulonglong2 w67 = *(const ulonglong2*)(wrow + 6);
        ulonglong2 w89 = *(const ulonglong2*)(wrow + 8);
        FMA2(acc[0], w01.x, da); FMA2(acc[1], w01.y, da);
        FMA2(acc[2], w23.x, da); FMA2(acc[3], w23.y, da);
        FMA2(acc[4], w45.x, da); FMA2(acc[5], w45.y, da);
        FMA2(acc[6], w67.x, da); FMA2(acc[7], w67.y, da);
        FMA2(acc[8], w89.x, da); FMA2(acc[9], w89.y, da);
    }
    float ao[20];
#pragma unroll
    for (int q = 0; q < 10; q++) UNPACK2(ao[2*q], ao[2*q+1], acc[q]);
    const int p = b*HW + rem;
    float t = ao[0] + bia[0] + dm[p];
    out[p] = fmaxf(t, 0.f) + log1pf(expf(-fabsf(t)));
    out[BHW   + p] = sxp[p] + (ao[1] + bia[1])*0.1f;
    out[2*BHW + p] = syp[p] + (ao[2] + bia[2])*0.1f;
#pragma unroll
    for (int j = 0; j < TFn; j++) {
        size_t fi = ((size_t)b*TFn + j)*HW + rem;
        out[3*(size_t)BHW + fi] = feat[fi] + ao[4+j] + bia[4+j];
    }
    float cz = ao[3] + bia[3] + 2.f*conf[p] - 1.f;
    out[19*(size_t)BHW + p] = 1.f / (1.f + expf(-cz));
}

// ---------------- launcher ----------------
extern "C" void kernel_launch(void* const* d_in, const int* in_sizes, int n_in,
                              void* d_out, int out_size)
{
    const float* dm   = (const float*)d_in[0];
    const float* sx   = (const float*)d_in[1];
    const float* sy   = (const float*)d_in[2];
    const float* feat = (const float*)d_in[3];
    const float* conf = (const float*)d_in[4];
    const float* fL   = (const float*)d_in[5];
    const float* fR   = (const float*)d_in[6];
    const float* w1   = (const float*)d_in[7];
    const float* w2   = (const float*)d_in[8];
    const float* w3   = (const float*)d_in[9];
    float* out = (float*)d_out;

    uint32_t *pxs, *phs; float *ph1, *ph2; uint4 *pB1, *pB2, *pB3;
    cudaGetSymbolAddress((void**)&pxs, g_xs);
    cudaGetSymbolAddress((void**)&phs, g_hs);
    cudaGetSymbolAddress((void**)&ph1, g_h1);
    cudaGetSymbolAddress((void**)&ph2, g_h2);
    cudaGetSymbolAddress((void**)&pB1, g_Bf1);
    cudaGetSymbolAddress((void**)&pB2, g_Bf2);
    cudaGetSymbolAddress((void**)&pB3, g_Bf3);

    const dim3 rgrid(Bn*HIDDEN, 8);
    const dim3 hgrid(HW/256, Bn);

    repack_frag_kernel<IN_CH, 4><<<(9*4*3*6*32 + 255)/256, 256>>>(w1, pB1);
    repack_frag_kernel<HIDDEN, 1><<<(9*1*3*6*32 + 255)/256, 256>>>(w2, pB2);
    repack_frag_kernel<HIDDEN, 1><<<(9*1*3*6*32 + 255)/256, 256>>>(w3, pB3);

    build_x_kernel<<<Bn*Hn, Wn>>>(dm, sx, sy, feat, conf, fL, fR);
    corr_pack_kernel<<<BHW/256, 256>>>();

    conv_hmma_kernel<4, XST><<<NT5, 256>>>(pxs, pB1, ph1);
    zero_stats_kernel<<<1, 64>>>();
    gn_reduce_kernel<<<rgrid, 256>>>(ph1);
    finalize_stats_kernel<<<1, 96>>>((const float*)d_in[10], (const float*)d_in[11]);
    hsplit_kernel<<<BHW/256, 256>>>(ph1, phs);

    conv_hmma_kernel<1, HIDDEN><<<NT5, 256>>>(phs, pB2, ph2);
    zero_stats_kernel<<<1, 64>>>();
    gn_reduce_kernel<<<rgrid, 256>>>(ph2);
    finalize_stats_kernel<<<1, 96>>>((const float*)d_in[12], (const float*)d_in[13]);
    hsplit_kernel<<<BHW/256, 256>>>(ph2, phs);

    conv_hmma_kernel<1, HIDDEN><<<NT5, 256>>>(phs, pB3, ph1);
    zero_stats_kernel<<<1, 64>>>();
    gn_reduce_kernel<<<rgrid, 256>>>(ph1);
    finalize_stats_kernel<<<1, 96>>>((const float*)d_in[14], (const float*)d_in[15]);

    heads_kernel<<<hgrid, 256>>>(ph1, dm, sx, sy, feat, conf,
                                 (const float*)d_in[16], (const float*)d_in[17],
                                 (const float*)d_in[18], (const float*)d_in[19],
                                 (const float*)d_in[20], (const float*)d_in[21],
                                 (const float*)d_in[22], (const float*)d_in[23],
                                 (const float*)d_in[24], (const float*)d_in[25], out);
}